// round 15
// baseline (speedup 1.0000x reference)
#include <cuda_runtime.h>
#include <cuda_bf16.h>
#include <math.h>
#include <stdint.h>

#define N_NODES 50000
#define N_EDGES 600000
#define DF      128
#define NC      47
#define LDC2    48

// ---------------- scratch ----------------------------------------------------
__device__ int   g_cnt[N_NODES];          // zero-init at load; self-cleaned by k_fill
__device__ int   g_rowptr[N_NODES + 1];
__device__ int   g_ord[N_EDGES];
__device__ int   g_col[N_EDGES];
__device__ float g_deginv[N_NODES];
__device__ volatile int g_agg[64];        // self-cleaned by k_fill
__device__ volatile int g_flag[64];       // self-cleaned by k_fill
__device__ __nv_bfloat16 g_P [N_NODES * DF];
__device__ __nv_bfloat16 g_R [N_NODES * DF];
__device__ __nv_bfloat16 g_H1[N_NODES * DF];
__device__ __nv_bfloat16 g_H2[N_NODES * DF];
// pre-packed bf16 k-major weight images, row stride 136:
// L0 @0 (256*136), L1 @34816, L2 @69632 (96*136)
__device__ __nv_bfloat16 g_Bt[82688];

// ---------------- helpers -----------------------------------------------------
__device__ __forceinline__ float4 ld_bf4(const __nv_bfloat16* p) {
    uint2 u = *(const uint2*)p;
    __nv_bfloat162 a = *(__nv_bfloat162*)&u.x;
    __nv_bfloat162 b = *(__nv_bfloat162*)&u.y;
    float2 fa = __bfloat1622float2(a), fb = __bfloat1622float2(b);
    return make_float4(fa.x, fa.y, fb.x, fb.y);
}
__device__ __forceinline__ void st_bf4(__nv_bfloat16* p, float4 v) {
    __nv_bfloat162 a = __floats2bfloat162_rn(v.x, v.y);
    __nv_bfloat162 b = __floats2bfloat162_rn(v.z, v.w);
    uint2 u;
    u.x = *(uint32_t*)&a; u.y = *(uint32_t*)&b;
    *(uint2*)p = u;
}
__device__ __forceinline__ uint32_t pack_bf2(float x, float y) {
    __nv_bfloat162 a = __floats2bfloat162_rn(x, y);
    return *(uint32_t*)&a;
}
__device__ __forceinline__ uint32_t smem_u32(const void* p) {
    uint32_t a;
    asm("{ .reg .u64 t; cvta.to.shared.u64 t, %1; cvt.u32.u64 %0, t; }" : "=r"(a) : "l"(p));
    return a;
}
__device__ __forceinline__ void ldsm_x4(uint32_t& r0, uint32_t& r1, uint32_t& r2,
                                        uint32_t& r3, uint32_t a) {
    asm volatile("ldmatrix.sync.aligned.m8n8.x4.shared.b16 {%0,%1,%2,%3}, [%4];"
                 : "=r"(r0), "=r"(r1), "=r"(r2), "=r"(r3) : "r"(a));
}
__device__ __forceinline__ void ldsm_x2(uint32_t& r0, uint32_t& r1, uint32_t a) {
    asm volatile("ldmatrix.sync.aligned.m8n8.x2.shared.b16 {%0,%1}, [%2];"
                 : "=r"(r0), "=r"(r1) : "r"(a));
}
__device__ __forceinline__ void mma_bf16(float* d, const uint32_t* a, const uint32_t* b) {
    asm volatile(
        "mma.sync.aligned.m16n8k16.row.col.f32.bf16.bf16.f32 "
        "{%0,%1,%2,%3},{%4,%5,%6,%7},{%8,%9},{%0,%1,%2,%3};"
        : "+f"(d[0]), "+f"(d[1]), "+f"(d[2]), "+f"(d[3])
        : "r"(a[0]), "r"(a[1]), "r"(a[2]), "r"(a[3]), "r"(b[0]), "r"(b[1]));
}
__device__ __forceinline__ void cp_async16(uint32_t dst, const void* src, int sz) {
    asm volatile("cp.async.ca.shared.global [%0], [%1], 16, %2;"
                 :: "r"(dst), "l"(src), "r"(sz) : "memory");
}
#define CP_COMMIT() asm volatile("cp.async.commit_group;" ::: "memory")
#define CP_WAIT0()  asm volatile("cp.async.wait_group 0;" ::: "memory")

// per-block int64/int32 discriminator: for int64 edge_index the odd 32-bit
// words are high halves (all 0, indices < 2^31); for int32 they are 64 random
// node ids — never all zero. Broadcast-cached reads, ~100ns per block.
__device__ __forceinline__ int detect_is64(const int* __restrict__ w, int* s_flag) {
    if (threadIdx.x < 32) {
        int bad = 0;
        #pragma unroll
        for (int j = threadIdx.x; j < 64; j += 32)
            bad |= (w[2 * j + 1] != 0);
        unsigned m = __ballot_sync(0xffffffffu, bad);
        if (threadIdx.x == 0) *s_flag = (m == 0) ? 1 : 0;
    }
    __syncthreads();
    return *s_flag;
}

// paired edge readers (e even; contiguous pairs vectorize)
__device__ __forceinline__ int2 edge_dst2(const int* __restrict__ w, int e, int is64) {
    if (is64) {
        int4 v = *(const int4*)(w + 2 * (N_EDGES + e));
        return make_int2(v.x, v.z);
    }
    return *(const int2*)(w + N_EDGES + e);
}
__device__ __forceinline__ int2 edge_src2(const int* __restrict__ w, int e, int is64) {
    if (is64) {
        int4 v = *(const int4*)(w + 2 * e);
        return make_int2(v.x, v.z);
    }
    return *(const int2*)(w + e);
}

// ------- weight prep, ALL layers (runs on main stream, parallel to CSR) ------
__global__ void k_prepB(const float* __restrict__ Wl0, const float* __restrict__ Wr0,
                        const float* __restrict__ Wl1, const float* __restrict__ Wr1,
                        const float* __restrict__ Wl2, const float* __restrict__ Wr2)
{
    int i = blockIdx.x * blockDim.x + threadIdx.x;
    if (i >= 77824) return;
    const float *Wl, *Wr;
    __nv_bfloat16* out;
    int NPER, F, li;
    if (i < 32768)      { li = i;         Wl = Wl0; Wr = Wr0; out = g_Bt;         NPER = 128; F = 128; }
    else if (i < 65536) { li = i - 32768; Wl = Wl1; Wr = Wr1; out = g_Bt + 34816; NPER = 128; F = 128; }
    else                { li = i - 65536; Wl = Wl2; Wr = Wr2; out = g_Bt + 69632; NPER = 48;  F = 47;  }
    int n = li >> 7, k = li & 127;
    int col = (n < NPER) ? n : n - NPER;
    const float* W = (n < NPER) ? Wl : Wr;
    float v = (col < F) ? W[(size_t)k * F + col] : 0.f;
    out[(size_t)n * 136 + k] = __float2bfloat16_rn(v);
}

// hist + ordinal capture, 2 edges/thread, inline dtype detect
__global__ void k_hist(const int* __restrict__ w) {
    __shared__ int s64;
    int is64 = detect_is64(w, &s64);
    int p = blockIdx.x * blockDim.x + threadIdx.x;
    int e = p * 2;
    if (e < N_EDGES) {
        int2 d = edge_dst2(w, e, is64);
        int o0 = atomicAdd(&g_cnt[d.x], 1);
        int o1 = atomicAdd(&g_cnt[d.y], 1);
        *(int2*)(g_ord + e) = make_int2(o0, o1);
    }
}

// single-pass scan with cross-block lookback (49 blocks, all resident)
__global__ void k_scan_lb() {
    __shared__ int wsum[32];
    __shared__ int s_ex;
    int b = blockIdx.x;
    int i = b * 1024 + threadIdx.x;
    int lane = threadIdx.x & 31, warp = threadIdx.x >> 5;
    int v = (i < N_NODES) ? g_cnt[i] : 0;
    int s = v;
    #pragma unroll
    for (int off = 1; off < 32; off <<= 1) {
        int t = __shfl_up_sync(0xffffffffu, s, off);
        if (lane >= off) s += t;
    }
    if (lane == 31) wsum[warp] = s;
    __syncthreads();
    if (warp == 0) {
        int ws = wsum[lane];
        #pragma unroll
        for (int off = 1; off < 32; off <<= 1) {
            int t = __shfl_up_sync(0xffffffffu, ws, off);
            if (lane >= off) ws += t;
        }
        wsum[lane] = ws;
    }
    __syncthreads();
    int incl = s + (warp ? wsum[warp - 1] : 0);
    if (threadIdx.x == 1023) {
        g_agg[b] = incl;
        __threadfence();
        g_flag[b] = 1;
    }
    if (warp == 0) {
        int ex = 0;
        for (int j = lane; j < b; j += 32) {
            while (g_flag[j] == 0) { }
            ex += g_agg[j];
        }
        #pragma unroll
        for (int o = 16; o; o >>= 1) ex += __shfl_xor_sync(0xffffffffu, ex, o);
        if (lane == 0) s_ex = ex;
    }
    __syncthreads();
    int r = s_ex + incl - v;
    if (i < N_NODES) {
        g_rowptr[i] = r;
        g_deginv[i] = 1.0f / (float)(v > 1 ? v : 1);
    }
    if (i == 0) g_rowptr[N_NODES] = N_EDGES;
}

// atomic-free fill, 2 edges/thread, inline detect; self-cleans scratch for the
// next identical call (device globals are zero-init on first use)
__global__ void k_fill(const int* __restrict__ w) {
    __shared__ int s64;
    int is64 = detect_is64(w, &s64);
    int p = blockIdx.x * blockDim.x + threadIdx.x;
    int e = p * 2;
    if (e < N_EDGES) {
        int2 d = edge_dst2(w, e, is64);
        int2 s = edge_src2(w, e, is64);
        int2 o = *(const int2*)(g_ord + e);
        g_col[g_rowptr[d.x] + o.x] = s.x;
        g_col[g_rowptr[d.y] + o.y] = s.y;
    }
    if (p < N_NODES) g_cnt[p] = 0;           // runs after scan consumed g_cnt
    if (p < 64) { g_flag[p] = 0; g_agg[p] = 0; }
}

// ---------------- one-shot dual GEMM for layer 0 (fp32 input; hidden by CSR) -
__global__ void __launch_bounds__(512, 1)
k_gemm0(const float* __restrict__ A, const __nv_bfloat16* __restrict__ Bimg,
        __nv_bfloat16* __restrict__ P, __nv_bfloat16* __restrict__ R)
{
    constexpr int AST = 136, BST = 136, BN = 256, NW = 64, NJ = 8;
    extern __shared__ __nv_bfloat16 smh[];
    __nv_bfloat16* As = smh;
    __nv_bfloat16* Bs = smh + 128 * AST;

    int bm = blockIdx.x * 128;
    int t  = threadIdx.x;

    #pragma unroll
    for (int it = 0; it < 8; it++) {
        int lin = t + it * 512;
        int row = lin >> 5, c4 = (lin & 31) << 2;
        float4 v = make_float4(0.f, 0.f, 0.f, 0.f);
        if (bm + row < N_NODES) v = *(const float4*)(A + (size_t)(bm + row) * DF + c4);
        uint2 u;
        u.x = pack_bf2(v.x, v.y);
        u.y = pack_bf2(v.z, v.w);
        *(uint2*)(As + row * AST + c4) = u;
    }
    {
        constexpr int CH = BN * BST * 2 / 16;
        const uint4* src = (const uint4*)Bimg;
        uint4* dst = (uint4*)Bs;
        #pragma unroll 4
        for (int i = t; i < CH; i += 512) dst[i] = src[i];
    }
    __syncthreads();

    int warp = t >> 5, lane = t & 31;
    int wm = (warp & 3) * 32;
    int wn = (warp >> 2) * NW;
    int group = lane >> 2, tig = lane & 3;
    int l8 = lane & 7, seg = lane >> 3;

    uint32_t sbA = smem_u32(As), sbB = smem_u32(Bs);
    uint32_t aAddr[2];
    #pragma unroll
    for (int i = 0; i < 2; i++)
        aAddr[i] = sbA + (uint32_t)(((wm + i * 16 + l8 + (seg & 1) * 8) * AST
                                     + (seg >> 1) * 8) * 2);
    uint32_t bAddr[NJ / 2];
    #pragma unroll
    for (int jj = 0; jj < NJ / 2; jj++)
        bAddr[jj] = sbB + (uint32_t)(((wn + (2 * jj + (seg >> 1)) * 8 + l8) * BST
                                      + (seg & 1) * 8) * 2);

    float acc[2][NJ][4];
    #pragma unroll
    for (int i = 0; i < 2; i++)
        #pragma unroll
        for (int j = 0; j < NJ; j++)
            #pragma unroll
            for (int q = 0; q < 4; q++) acc[i][j][q] = 0.f;

    #pragma unroll
    for (int k0 = 0; k0 < DF; k0 += 16) {
        uint32_t a[2][4], b[NJ][2];
        #pragma unroll
        for (int i = 0; i < 2; i++)
            ldsm_x4(a[i][0], a[i][1], a[i][2], a[i][3], aAddr[i] + k0 * 2);
        #pragma unroll
        for (int jj = 0; jj < NJ / 2; jj++)
            ldsm_x4(b[2 * jj][0], b[2 * jj][1], b[2 * jj + 1][0], b[2 * jj + 1][1],
                    bAddr[jj] + k0 * 2);
        #pragma unroll
        for (int i = 0; i < 2; i++)
            #pragma unroll
            for (int j = 0; j < NJ; j++)
                mma_bf16(acc[i][j], a[i], b[j]);
    }

    #pragma unroll
    for (int i = 0; i < 2; i++) {
        int gm0 = bm + wm + i * 16 + group;
        #pragma unroll
        for (int j = 0; j < NJ; j++) {
            int gn = wn + j * 8 + 2 * tig;
            __nv_bfloat16* dst = (gn < 128) ? P : R;
            int col = (gn < 128) ? gn : gn - 128;
            if (gm0 < N_NODES)
                *(uint32_t*)(dst + (size_t)gm0 * DF + col) = pack_bf2(acc[i][j][0], acc[i][j][1]);
            if (gm0 + 8 < N_NODES)
                *(uint32_t*)(dst + (size_t)(gm0 + 8) * DF + col) = pack_bf2(acc[i][j][2], acc[i][j][3]);
        }
    }
}

// ------- persistent double-buffered dual GEMM (bf16 input, cp.async) ---------
template<int NPER>
__global__ void __launch_bounds__(512, 1)
k_gemm_p(const __nv_bfloat16* __restrict__ A, const __nv_bfloat16* __restrict__ Bimg,
         __nv_bfloat16* __restrict__ P, __nv_bfloat16* __restrict__ R,
         int F, int ntiles)
{
    constexpr int BN   = 2 * NPER;
    constexpr int NW   = BN / 4;
    constexpr int NJ   = NW / 8;
    constexpr int AST  = 136, BST = 136;
    constexpr int ABUF = 128 * AST;
    extern __shared__ __nv_bfloat16 smh[];
    __nv_bfloat16* Bs = smh;
    __nv_bfloat16* As = smh + BN * BST;

    int t = threadIdx.x;
    uint32_t sbB = smem_u32(Bs), sbA = smem_u32(As);

    {
        constexpr int CHB = BN * BST * 2 / 16;
        for (int i = t; i < CHB; i += 512)
            cp_async16(sbB + i * 16, (const char*)Bimg + i * 16, 16);
        int tile0 = blockIdx.x;
        if (tile0 < ntiles) {
            int bm = tile0 * 128;
            #pragma unroll
            for (int it = 0; it < 4; it++) {
                int lin = t + it * 512;
                int row = lin >> 4, c8 = (lin & 15) << 3;
                int gr = bm + row;
                int ok = (gr < N_NODES) ? 16 : 0;
                int gc = (gr < N_NODES) ? gr : (N_NODES - 1);
                cp_async16(sbA + (uint32_t)(row * AST + c8) * 2,
                           A + (size_t)gc * DF + c8, ok);
            }
        }
        CP_COMMIT();
    }

    int warp = t >> 5, lane = t & 31;
    int wm = (warp & 3) * 32;
    int wn = (warp >> 2) * NW;
    int group = lane >> 2, tig = lane & 3;
    int l8 = lane & 7, seg = lane >> 3;

    uint32_t aOff[2];
    #pragma unroll
    for (int i = 0; i < 2; i++)
        aOff[i] = sbA + (uint32_t)(((wm + i * 16 + l8 + (seg & 1) * 8) * AST
                                    + (seg >> 1) * 8) * 2);
    uint32_t bAddr[(NJ + 1) / 2];
    #pragma unroll
    for (int jj = 0; jj < NJ / 2; jj++)
        bAddr[jj] = sbB + (uint32_t)(((wn + (2 * jj + (seg >> 1)) * 8 + l8) * BST
                                      + (seg & 1) * 8) * 2);
    if constexpr (NJ & 1)
        bAddr[NJ / 2] = sbB + (uint32_t)(((wn + (NJ - 1) * 8 + l8) * BST
                                          + (seg & 1) * 8) * 2);

    int buf = 0;
    for (int tile = blockIdx.x; tile < ntiles; tile += gridDim.x) {
        CP_WAIT0();
        __syncthreads();

        int nxt = tile + gridDim.x;
        if (nxt < ntiles) {
            int bm = nxt * 128;
            uint32_t dstb = sbA + (uint32_t)((buf ^ 1) * ABUF) * 2;
            #pragma unroll
            for (int it = 0; it < 4; it++) {
                int lin = t + it * 512;
                int row = lin >> 4, c8 = (lin & 15) << 3;
                int gr = bm + row;
                int ok = (gr < N_NODES) ? 16 : 0;
                int gc = (gr < N_NODES) ? gr : (N_NODES - 1);
                cp_async16(dstb + (uint32_t)(row * AST + c8) * 2,
                           A + (size_t)gc * DF + c8, ok);
            }
        }
        CP_COMMIT();

        uint32_t abase = (uint32_t)(buf * ABUF) * 2;
        float acc[2][NJ][4];
        #pragma unroll
        for (int i = 0; i < 2; i++)
            #pragma unroll
            for (int j = 0; j < NJ; j++)
                #pragma unroll
                for (int q = 0; q < 4; q++) acc[i][j][q] = 0.f;

        #pragma unroll
        for (int k0 = 0; k0 < DF; k0 += 16) {
            uint32_t a[2][4], b[NJ][2];
            #pragma unroll
            for (int i = 0; i < 2; i++)
                ldsm_x4(a[i][0], a[i][1], a[i][2], a[i][3], aOff[i] + abase + k0 * 2);
            #pragma unroll
            for (int jj = 0; jj < NJ / 2; jj++)
                ldsm_x4(b[2 * jj][0], b[2 * jj][1], b[2 * jj + 1][0], b[2 * jj + 1][1],
                        bAddr[jj] + k0 * 2);
            if constexpr (NJ & 1)
                ldsm_x2(b[NJ - 1][0], b[NJ - 1][1], bAddr[NJ / 2] + k0 * 2);
            #pragma unroll
            for (int i = 0; i < 2; i++)
                #pragma unroll
                for (int j = 0; j < NJ; j++)
                    mma_bf16(acc[i][j], a[i], b[j]);
        }

        int bm = tile * 128;
        #pragma unroll
        for (int i = 0; i < 2; i++) {
            int gm0 = bm + wm + i * 16 + group;
            #pragma unroll
            for (int j = 0; j < NJ; j++) {
                int gn = wn + j * 8 + 2 * tig;
                __nv_bfloat16* dst;
                int col;
                if (gn < NPER) { dst = P; col = gn; }
                else           { dst = R; col = gn - NPER; }
                float v0 = (col     < F) ? acc[i][j][0] : 0.f;
                float v1 = (col + 1 < F) ? acc[i][j][1] : 0.f;
                float v2 = (col     < F) ? acc[i][j][2] : 0.f;
                float v3 = (col + 1 < F) ? acc[i][j][3] : 0.f;
                if (gm0 < N_NODES)
                    *(uint32_t*)(dst + (size_t)gm0 * NPER + col) = pack_bf2(v0, v1);
                if (gm0 + 8 < N_NODES)
                    *(uint32_t*)(dst + (size_t)(gm0 + 8) * NPER + col) = pack_bf2(v2, v3);
            }
        }
        buf ^= 1;
    }
}

// -------- aggregation (hidden): OUT = relu(mean_nbr(P)+b+R) -----------------
__global__ void k_aggr(const __nv_bfloat16* __restrict__ P,
                       const __nv_bfloat16* __restrict__ R,
                       const float* __restrict__ bias,
                       __nv_bfloat16* __restrict__ OUT)
{
    int gw   = (blockIdx.x * blockDim.x + threadIdx.x) >> 5;
    int lane = threadIdx.x & 31;
    if (gw >= N_NODES) return;
    int start = g_rowptr[gw], end = g_rowptr[gw + 1];

    int c0 = lane << 2;
    const __nv_bfloat16* base = P + c0;
    float4 a0 = make_float4(0.f, 0.f, 0.f, 0.f);
    float4 a1 = make_float4(0.f, 0.f, 0.f, 0.f);
    int e = start;
    for (; e + 4 <= end; e += 4) {
        int i0 = g_col[e], i1 = g_col[e + 1], i2 = g_col[e + 2], i3 = g_col[e + 3];
        float4 p0 = ld_bf4(base + (size_t)i0 * DF);
        float4 p1 = ld_bf4(base + (size_t)i1 * DF);
        float4 p2 = ld_bf4(base + (size_t)i2 * DF);
        float4 p3 = ld_bf4(base + (size_t)i3 * DF);
        a0.x += p0.x; a0.y += p0.y; a0.z += p0.z; a0.w += p0.w;
        a1.x += p1.x; a1.y += p1.y; a1.z += p1.z; a1.w += p1.w;
        a0.x += p2.x; a0.y += p2.y; a0.z += p2.z; a0.w += p2.w;
        a1.x += p3.x; a1.y += p3.y; a1.z += p3.z; a1.w += p3.w;
    }
    for (; e < end; e++) {
        float4 p = ld_bf4(base + (size_t)g_col[e] * DF);
        a0.x += p.x; a0.y += p.y; a0.z += p.z; a0.w += p.w;
    }
    float inv = g_deginv[gw];
    float4 r = ld_bf4(R + (size_t)gw * DF + c0);
    float4 b = *(const float4*)(bias + c0);
    float4 ov;
    ov.x = fmaxf((a0.x + a1.x) * inv + b.x + r.x, 0.f);
    ov.y = fmaxf((a0.y + a1.y) * inv + b.y + r.y, 0.f);
    ov.z = fmaxf((a0.z + a1.z) * inv + b.z + r.z, 0.f);
    ov.w = fmaxf((a0.w + a1.w) * inv + b.w + r.w, 0.f);
    st_bf4(OUT + (size_t)gw * DF + c0, ov);
}

// -------- fused layer-2: aggr + L2-normalize + log_softmax ------------------
__global__ void k_aggr_out(const __nv_bfloat16* __restrict__ P,
                           const __nv_bfloat16* __restrict__ R,
                           const float* __restrict__ bias,
                           float* __restrict__ out)
{
    int gw   = (blockIdx.x * blockDim.x + threadIdx.x) >> 5;
    int lane = threadIdx.x & 31;
    if (gw >= N_NODES) return;
    bool act = (lane < 12);
    int c0 = lane << 2;

    float v[4] = {0.f, 0.f, 0.f, 0.f};
    if (act) {
        int start = g_rowptr[gw], end = g_rowptr[gw + 1];
        const __nv_bfloat16* base = P + c0;
        float4 a0 = make_float4(0.f, 0.f, 0.f, 0.f);
        float4 a1 = make_float4(0.f, 0.f, 0.f, 0.f);
        int e = start;
        for (; e + 4 <= end; e += 4) {
            int i0 = g_col[e], i1 = g_col[e + 1], i2 = g_col[e + 2], i3 = g_col[e + 3];
            float4 p0 = ld_bf4(base + (size_t)i0 * LDC2);
            float4 p1 = ld_bf4(base + (size_t)i1 * LDC2);
            float4 p2 = ld_bf4(base + (size_t)i2 * LDC2);
            float4 p3 = ld_bf4(base + (size_t)i3 * LDC2);
            a0.x += p0.x; a0.y += p0.y; a0.z += p0.z; a0.w += p0.w;
            a1.x += p1.x; a1.y += p1.y; a1.z += p1.z; a1.w += p1.w;
            a0.x += p2.x; a0.y += p2.y; a0.z += p2.z; a0.w += p2.w;
            a1.x += p3.x; a1.y += p3.y; a1.z += p3.z; a1.w += p3.w;
        }
        for (; e < end; e++) {
            float4 p = ld_bf4(base + (size_t)g_col[e] * LDC2);
            a0.x += p.x; a0.y += p.y; a0.z += p.z; a0.w += p.w;
        }
        float inv = g_deginv[gw];
        float4 r = ld_bf4(R + (size_t)gw * LDC2 + c0);
        float av[4] = {a0.x + a1.x, a0.y + a1.y, a0.z + a1.z, a0.w + a1.w};
        float rv[4] = {r.x, r.y, r.z, r.w};
        #pragma unroll
        for (int j = 0; j < 4; j++) {
            int cc = c0 + j;
            if (cc < NC) v[j] = av[j] * inv + bias[cc] + rv[j];
        }
    }

    float ss = v[0]*v[0] + v[1]*v[1] + v[2]*v[2] + v[3]*v[3];
    #pragma unroll
    for (int o = 16; o; o >>= 1) ss += __shfl_xor_sync(0xffffffffu, ss, o);
    float inv = 1.0f / fmaxf(sqrtf(ss), 1e-12f);
    #pragma unroll
    for (int j = 0; j < 4; j++) v[j] *= inv;

    float m = -1e30f;
    #pragma unroll
    for (int j = 0; j < 4; j++)
        if (act && (c0 + j) < NC) m = fmaxf(m, v[j]);
    #pragma unroll
    for (int o = 16; o; o >>= 1) m = fmaxf(m, __shfl_xor_sync(0xffffffffu, m, o));

    float s = 0.f;
    #pragma unroll
    for (int j = 0; j < 4; j++)
        if (act && (c0 + j) < NC) s += expf(v[j] - m);
    #pragma unroll
    for (int o = 16; o; o >>= 1) s += __shfl_xor_sync(0xffffffffu, s, o);
    float ls = m + logf(s);

    if (act) {
        #pragma unroll
        for (int j = 0; j < 4; j++) {
            int cc = c0 + j;
            if (cc < NC) out[(size_t)gw * NC + cc] = v[j] - ls;
        }
    }
}

// ---------------- host --------------------------------------------------------
extern "C" void kernel_launch(void* const* d_in, const int* in_sizes, int n_in,
                              void* d_out, int out_size)
{
    const float* x   = (const float*)d_in[0];
    const int*   ei  = (const int*)  d_in[1];
    const float* Wl0 = (const float*)d_in[2];
    const float* bl0 = (const float*)d_in[3];
    const float* Wr0 = (const float*)d_in[4];
    const float* Wl1 = (const float*)d_in[5];
    const float* bl1 = (const float*)d_in[6];
    const float* Wr1 = (const float*)d_in[7];
    const float* Wl2 = (const float*)d_in[8];
    const float* bl2 = (const float*)d_in[9];
    const float* Wr2 = (const float*)d_in[10];
    float* out = (float*)d_out;

    __nv_bfloat16 *P, *R, *H1, *H2, *Bt;
    cudaGetSymbolAddress((void**)&P,  g_P);
    cudaGetSymbolAddress((void**)&R,  g_R);
    cudaGetSymbolAddress((void**)&H1, g_H1);
    cudaGetSymbolAddress((void**)&H2, g_H2);
    cudaGetSymbolAddress((void**)&Bt, g_Bt);

    const int SMEM_G0   = (128 * 136 + 256 * 136) * 2;            // 104448
    const int SMEM_P128 = (256 * 136 + 2 * 128 * 136) * 2;        // 139264
    const int SMEM_P48  = ( 96 * 136 + 2 * 128 * 136) * 2;        //  95744
    cudaFuncSetAttribute(k_gemm0,       cudaFuncAttributeMaxDynamicSharedMemorySize, SMEM_G0);
    cudaFuncSetAttribute(k_gemm_p<128>, cudaFuncAttributeMaxDynamicSharedMemorySize, SMEM_P128);
    cudaFuncSetAttribute(k_gemm_p<48>,  cudaFuncAttributeMaxDynamicSharedMemorySize, SMEM_P48);

    static cudaStream_t s1 = 0;
    static cudaEvent_t evFork = 0, evCSR = 0;
    if (!s1) {
        cudaStreamCreateWithFlags(&s1, cudaStreamNonBlocking);
        cudaEventCreateWithFlags(&evFork, cudaEventDisableTiming);
        cudaEventCreateWithFlags(&evCSR,  cudaEventDisableTiming);
    }

    int gmb = (N_NODES + 127) / 128;       // 391 tiles
    int agb = (N_NODES * 32 + 255) / 256;
    int epb = (N_EDGES / 2 + 255) / 256;   // 2 edges/thread

    // empty fork edge (required for capture): no kernel ahead of it
    cudaEventRecord(evFork, 0);
    cudaStreamWaitEvent(s1, evFork, 0);

    // side stream: CSR build starts immediately (counters self-cleaned by the
    // previous call's k_fill; dtype detect is inlined per-block)
    k_hist<<<epb, 256, 0, s1>>>(ei);
    k_scan_lb<<<(N_NODES + 1023) / 1024, 1024, 0, s1>>>();
    k_fill<<<epb, 256, 0, s1>>>(ei);
    cudaEventRecord(evCSR, s1);

    // main stream (parallel to CSR): weight images ONCE, then layer-0 GEMM
    k_prepB<<<(77824 + 255) / 256, 256>>>(Wl0, Wr0, Wl1, Wr1, Wl2, Wr2);
    k_gemm0<<<gmb, 512, SMEM_G0>>>(x, Bt, P, R);

    cudaStreamWaitEvent(0, evCSR, 0);
    k_aggr<<<agb, 256>>>(P, R, bl0, H1);
    // layer 1: persistent double-buffered GEMM
    k_gemm_p<128><<<152, 512, SMEM_P128>>>(H1, Bt + 34816, P, R, DF, gmb);
    k_aggr<<<agb, 256>>>(P, R, bl1, H2);
    // layer 2 (47 padded to 48)
    k_gemm_p<48><<<152, 512, SMEM_P48>>>(H2, Bt + 69632, P, R, NC, gmb);
    k_aggr_out<<<agb, 256>>>(P, R, bl2, out);
}

// round 16
// speedup vs baseline: 1.0323x; 1.0323x over previous
#include <cuda_runtime.h>
#include <cuda_bf16.h>
#include <math.h>
#include <stdint.h>

#define N_NODES 50000
#define N_EDGES 600000
#define DF      128
#define NC      47
#define LDC2    48

// ---------------- scratch ----------------------------------------------------
__device__ int   g_cnt[N_NODES];          // zero-init at load; self-cleaned by k_fill
__device__ int   g_rowptr[N_NODES + 1];
__device__ int   g_ord[N_EDGES];
__device__ int   g_col[N_EDGES];
__device__ float g_deginv[N_NODES];
__device__ volatile int g_agg[64];        // self-cleaned by k_fill
__device__ volatile int g_flag[64];       // self-cleaned by k_fill
__device__ __nv_bfloat16 g_P [N_NODES * DF];
__device__ __nv_bfloat16 g_R [N_NODES * DF];
__device__ __nv_bfloat16 g_H1[N_NODES * DF];
__device__ __nv_bfloat16 g_H2[N_NODES * DF];
// pre-packed bf16 k-major weight images, row stride 136:
// L0 @0 (256*136), L1 @34816, L2 @69632 (96*136)
__device__ __nv_bfloat16 g_Bt[82688];

// ---------------- helpers -----------------------------------------------------
__device__ __forceinline__ float4 ld_bf4(const __nv_bfloat16* p) {
    uint2 u = *(const uint2*)p;
    __nv_bfloat162 a = *(__nv_bfloat162*)&u.x;
    __nv_bfloat162 b = *(__nv_bfloat162*)&u.y;
    float2 fa = __bfloat1622float2(a), fb = __bfloat1622float2(b);
    return make_float4(fa.x, fa.y, fb.x, fb.y);
}
__device__ __forceinline__ void st_bf4(__nv_bfloat16* p, float4 v) {
    __nv_bfloat162 a = __floats2bfloat162_rn(v.x, v.y);
    __nv_bfloat162 b = __floats2bfloat162_rn(v.z, v.w);
    uint2 u;
    u.x = *(uint32_t*)&a; u.y = *(uint32_t*)&b;
    *(uint2*)p = u;
}
__device__ __forceinline__ uint32_t pack_bf2(float x, float y) {
    __nv_bfloat162 a = __floats2bfloat162_rn(x, y);
    return *(uint32_t*)&a;
}
__device__ __forceinline__ uint32_t smem_u32(const void* p) {
    uint32_t a;
    asm("{ .reg .u64 t; cvta.to.shared.u64 t, %1; cvt.u32.u64 %0, t; }" : "=r"(a) : "l"(p));
    return a;
}
__device__ __forceinline__ void ldsm_x4(uint32_t& r0, uint32_t& r1, uint32_t& r2,
                                        uint32_t& r3, uint32_t a) {
    asm volatile("ldmatrix.sync.aligned.m8n8.x4.shared.b16 {%0,%1,%2,%3}, [%4];"
                 : "=r"(r0), "=r"(r1), "=r"(r2), "=r"(r3) : "r"(a));
}
__device__ __forceinline__ void ldsm_x2(uint32_t& r0, uint32_t& r1, uint32_t a) {
    asm volatile("ldmatrix.sync.aligned.m8n8.x2.shared.b16 {%0,%1}, [%2];"
                 : "=r"(r0), "=r"(r1) : "r"(a));
}
__device__ __forceinline__ void mma_bf16(float* d, const uint32_t* a, const uint32_t* b) {
    asm volatile(
        "mma.sync.aligned.m16n8k16.row.col.f32.bf16.bf16.f32 "
        "{%0,%1,%2,%3},{%4,%5,%6,%7},{%8,%9},{%0,%1,%2,%3};"
        : "+f"(d[0]), "+f"(d[1]), "+f"(d[2]), "+f"(d[3])
        : "r"(a[0]), "r"(a[1]), "r"(a[2]), "r"(a[3]), "r"(b[0]), "r"(b[1]));
}
__device__ __forceinline__ void cp_async16(uint32_t dst, const void* src, int sz) {
    asm volatile("cp.async.ca.shared.global [%0], [%1], 16, %2;"
                 :: "r"(dst), "l"(src), "r"(sz) : "memory");
}
#define CP_COMMIT() asm volatile("cp.async.commit_group;" ::: "memory")
#define CP_WAIT0()  asm volatile("cp.async.wait_group 0;" ::: "memory")

// per-block int64/int32 discriminator (see R13 notes)
__device__ __forceinline__ int detect_is64(const int* __restrict__ w, int* s_flag) {
    if (threadIdx.x < 32) {
        int bad = 0;
        #pragma unroll
        for (int j = threadIdx.x; j < 64; j += 32)
            bad |= (w[2 * j + 1] != 0);
        unsigned m = __ballot_sync(0xffffffffu, bad);
        if (threadIdx.x == 0) *s_flag = (m == 0) ? 1 : 0;
    }
    __syncthreads();
    return *s_flag;
}

__device__ __forceinline__ int2 edge_dst2(const int* __restrict__ w, int e, int is64) {
    if (is64) {
        int4 v = *(const int4*)(w + 2 * (N_EDGES + e));
        return make_int2(v.x, v.z);
    }
    return *(const int2*)(w + N_EDGES + e);
}
__device__ __forceinline__ int2 edge_src2(const int* __restrict__ w, int e, int is64) {
    if (is64) {
        int4 v = *(const int4*)(w + 2 * e);
        return make_int2(v.x, v.z);
    }
    return *(const int2*)(w + e);
}

// ------- weight prep, ALL layers (runs on main stream, parallel to CSR) ------
__global__ void k_prepB(const float* __restrict__ Wl0, const float* __restrict__ Wr0,
                        const float* __restrict__ Wl1, const float* __restrict__ Wr1,
                        const float* __restrict__ Wl2, const float* __restrict__ Wr2)
{
    int i = blockIdx.x * blockDim.x + threadIdx.x;
    if (i >= 77824) return;
    const float *Wl, *Wr;
    __nv_bfloat16* out;
    int NPER, F, li;
    if (i < 32768)      { li = i;         Wl = Wl0; Wr = Wr0; out = g_Bt;         NPER = 128; F = 128; }
    else if (i < 65536) { li = i - 32768; Wl = Wl1; Wr = Wr1; out = g_Bt + 34816; NPER = 128; F = 128; }
    else                { li = i - 65536; Wl = Wl2; Wr = Wr2; out = g_Bt + 69632; NPER = 48;  F = 47;  }
    int n = li >> 7, k = li & 127;
    int col = (n < NPER) ? n : n - NPER;
    const float* W = (n < NPER) ? Wl : Wr;
    float v = (col < F) ? W[(size_t)k * F + col] : 0.f;
    out[(size_t)n * 136 + k] = __float2bfloat16_rn(v);
}

// hist + ordinal capture, 2 edges/thread, inline dtype detect
__global__ void k_hist(const int* __restrict__ w) {
    __shared__ int s64;
    int is64 = detect_is64(w, &s64);
    int p = blockIdx.x * blockDim.x + threadIdx.x;
    int e = p * 2;
    if (e < N_EDGES) {
        int2 d = edge_dst2(w, e, is64);
        int o0 = atomicAdd(&g_cnt[d.x], 1);
        int o1 = atomicAdd(&g_cnt[d.y], 1);
        *(int2*)(g_ord + e) = make_int2(o0, o1);
    }
}

// single-pass scan with cross-block lookback (49 blocks, all resident)
__global__ void k_scan_lb() {
    __shared__ int wsum[32];
    __shared__ int s_ex;
    int b = blockIdx.x;
    int i = b * 1024 + threadIdx.x;
    int lane = threadIdx.x & 31, warp = threadIdx.x >> 5;
    int v = (i < N_NODES) ? g_cnt[i] : 0;
    int s = v;
    #pragma unroll
    for (int off = 1; off < 32; off <<= 1) {
        int t = __shfl_up_sync(0xffffffffu, s, off);
        if (lane >= off) s += t;
    }
    if (lane == 31) wsum[warp] = s;
    __syncthreads();
    if (warp == 0) {
        int ws = wsum[lane];
        #pragma unroll
        for (int off = 1; off < 32; off <<= 1) {
            int t = __shfl_up_sync(0xffffffffu, ws, off);
            if (lane >= off) ws += t;
        }
        wsum[lane] = ws;
    }
    __syncthreads();
    int incl = s + (warp ? wsum[warp - 1] : 0);
    if (threadIdx.x == 1023) {
        g_agg[b] = incl;
        __threadfence();
        g_flag[b] = 1;
    }
    if (warp == 0) {
        int ex = 0;
        for (int j = lane; j < b; j += 32) {
            while (g_flag[j] == 0) { }
            ex += g_agg[j];
        }
        #pragma unroll
        for (int o = 16; o; o >>= 1) ex += __shfl_xor_sync(0xffffffffu, ex, o);
        if (lane == 0) s_ex = ex;
    }
    __syncthreads();
    int r = s_ex + incl - v;
    if (i < N_NODES) {
        g_rowptr[i] = r;
        g_deginv[i] = 1.0f / (float)(v > 1 ? v : 1);
    }
    if (i == 0) g_rowptr[N_NODES] = N_EDGES;
}

// atomic-free fill, 2 edges/thread, inline detect; self-cleans scratch
__global__ void k_fill(const int* __restrict__ w) {
    __shared__ int s64;
    int is64 = detect_is64(w, &s64);
    int p = blockIdx.x * blockDim.x + threadIdx.x;
    int e = p * 2;
    if (e < N_EDGES) {
        int2 d = edge_dst2(w, e, is64);
        int2 s = edge_src2(w, e, is64);
        int2 o = *(const int2*)(g_ord + e);
        g_col[g_rowptr[d.x] + o.x] = s.x;
        g_col[g_rowptr[d.y] + o.y] = s.y;
    }
    if (p < N_NODES) g_cnt[p] = 0;
    if (p < 64) { g_flag[p] = 0; g_agg[p] = 0; }
}

// ---------------- one-shot dual GEMM for layer 0 (fp32 input; hidden by CSR) -
__global__ void __launch_bounds__(512, 1)
k_gemm0(const float* __restrict__ A, const __nv_bfloat16* __restrict__ Bimg,
        __nv_bfloat16* __restrict__ P, __nv_bfloat16* __restrict__ R)
{
    constexpr int AST = 136, BST = 136, BN = 256, NW = 64, NJ = 8;
    extern __shared__ __nv_bfloat16 smh[];
    __nv_bfloat16* As = smh;
    __nv_bfloat16* Bs = smh + 128 * AST;

    int bm = blockIdx.x * 128;
    int t  = threadIdx.x;

    #pragma unroll
    for (int it = 0; it < 8; it++) {
        int lin = t + it * 512;
        int row = lin >> 5, c4 = (lin & 31) << 2;
        float4 v = make_float4(0.f, 0.f, 0.f, 0.f);
        if (bm + row < N_NODES) v = *(const float4*)(A + (size_t)(bm + row) * DF + c4);
        uint2 u;
        u.x = pack_bf2(v.x, v.y);
        u.y = pack_bf2(v.z, v.w);
        *(uint2*)(As + row * AST + c4) = u;
    }
    {
        constexpr int CH = BN * BST * 2 / 16;
        const uint4* src = (const uint4*)Bimg;
        uint4* dst = (uint4*)Bs;
        #pragma unroll 4
        for (int i = t; i < CH; i += 512) dst[i] = src[i];
    }
    __syncthreads();

    int warp = t >> 5, lane = t & 31;
    int wm = (warp & 3) * 32;
    int wn = (warp >> 2) * NW;
    int group = lane >> 2, tig = lane & 3;
    int l8 = lane & 7, seg = lane >> 3;

    uint32_t sbA = smem_u32(As), sbB = smem_u32(Bs);
    uint32_t aAddr[2];
    #pragma unroll
    for (int i = 0; i < 2; i++)
        aAddr[i] = sbA + (uint32_t)(((wm + i * 16 + l8 + (seg & 1) * 8) * AST
                                     + (seg >> 1) * 8) * 2);
    uint32_t bAddr[NJ / 2];
    #pragma unroll
    for (int jj = 0; jj < NJ / 2; jj++)
        bAddr[jj] = sbB + (uint32_t)(((wn + (2 * jj + (seg >> 1)) * 8 + l8) * BST
                                      + (seg & 1) * 8) * 2);

    float acc[2][NJ][4];
    #pragma unroll
    for (int i = 0; i < 2; i++)
        #pragma unroll
        for (int j = 0; j < NJ; j++)
            #pragma unroll
            for (int q = 0; q < 4; q++) acc[i][j][q] = 0.f;

    #pragma unroll
    for (int k0 = 0; k0 < DF; k0 += 16) {
        uint32_t a[2][4], b[NJ][2];
        #pragma unroll
        for (int i = 0; i < 2; i++)
            ldsm_x4(a[i][0], a[i][1], a[i][2], a[i][3], aAddr[i] + k0 * 2);
        #pragma unroll
        for (int jj = 0; jj < NJ / 2; jj++)
            ldsm_x4(b[2 * jj][0], b[2 * jj][1], b[2 * jj + 1][0], b[2 * jj + 1][1],
                    bAddr[jj] + k0 * 2);
        #pragma unroll
        for (int i = 0; i < 2; i++)
            #pragma unroll
            for (int j = 0; j < NJ; j++)
                mma_bf16(acc[i][j], a[i], b[j]);
    }

    #pragma unroll
    for (int i = 0; i < 2; i++) {
        int gm0 = bm + wm + i * 16 + group;
        #pragma unroll
        for (int j = 0; j < NJ; j++) {
            int gn = wn + j * 8 + 2 * tig;
            __nv_bfloat16* dst = (gn < 128) ? P : R;
            int col = (gn < 128) ? gn : gn - 128;
            if (gm0 < N_NODES)
                *(uint32_t*)(dst + (size_t)gm0 * DF + col) = pack_bf2(acc[i][j][0], acc[i][j][1]);
            if (gm0 + 8 < N_NODES)
                *(uint32_t*)(dst + (size_t)(gm0 + 8) * DF + col) = pack_bf2(acc[i][j][2], acc[i][j][3]);
        }
    }
}

// ------- persistent double-buffered dual GEMM, smem-staged epilogue ----------
// B image zero-pads cols >= F, so accumulators there are exactly 0 — the
// staged copy needs no F masking.
template<int NPER>
__global__ void __launch_bounds__(512, 1)
k_gemm_p(const __nv_bfloat16* __restrict__ A, const __nv_bfloat16* __restrict__ Bimg,
         __nv_bfloat16* __restrict__ P, __nv_bfloat16* __restrict__ R,
         int ntiles)
{
    constexpr int BN   = 2 * NPER;            // 256 or 96
    constexpr int NW   = BN / 4;
    constexpr int NJ   = NW / 8;
    constexpr int AST  = 136, BST = 136;
    constexpr int ABUF = 128 * AST;
    constexpr int BST2 = (NPER == 128) ? 264 : 104;   // staging stride (conflict-free)
    constexpr int CPR  = BN / 8;              // 16B chunks per staged row
    extern __shared__ __nv_bfloat16 smh[];
    __nv_bfloat16* Bs = smh;                  // [BN][BST]
    __nv_bfloat16* As = smh + BN * BST;       // [2][128][AST]
    __nv_bfloat16* St = As + 2 * ABUF;        // [128][BST2] epilogue staging

    int t = threadIdx.x;
    uint32_t sbB = smem_u32(Bs), sbA = smem_u32(As);

    {
        constexpr int CHB = BN * BST * 2 / 16;
        for (int i = t; i < CHB; i += 512)
            cp_async16(sbB + i * 16, (const char*)Bimg + i * 16, 16);
        int tile0 = blockIdx.x;
        if (tile0 < ntiles) {
            int bm = tile0 * 128;
            #pragma unroll
            for (int it = 0; it < 4; it++) {
                int lin = t + it * 512;
                int row = lin >> 4, c8 = (lin & 15) << 3;
                int gr = bm + row;
                int ok = (gr < N_NODES) ? 16 : 0;
                int gc = (gr < N_NODES) ? gr : (N_NODES - 1);
                cp_async16(sbA + (uint32_t)(row * AST + c8) * 2,
                           A + (size_t)gc * DF + c8, ok);
            }
        }
        CP_COMMIT();
    }

    int warp = t >> 5, lane = t & 31;
    int wm = (warp & 3) * 32;
    int wn = (warp >> 2) * NW;
    int group = lane >> 2, tig = lane & 3;
    int l8 = lane & 7, seg = lane >> 3;

    uint32_t aOff[2];
    #pragma unroll
    for (int i = 0; i < 2; i++)
        aOff[i] = sbA + (uint32_t)(((wm + i * 16 + l8 + (seg & 1) * 8) * AST
                                    + (seg >> 1) * 8) * 2);
    uint32_t bAddr[(NJ + 1) / 2];
    #pragma unroll
    for (int jj = 0; jj < NJ / 2; jj++)
        bAddr[jj] = sbB + (uint32_t)(((wn + (2 * jj + (seg >> 1)) * 8 + l8) * BST
                                      + (seg & 1) * 8) * 2);
    if constexpr (NJ & 1)
        bAddr[NJ / 2] = sbB + (uint32_t)(((wn + (NJ - 1) * 8 + l8) * BST
                                          + (seg & 1) * 8) * 2);

    int buf = 0;
    for (int tile = blockIdx.x; tile < ntiles; tile += gridDim.x) {
        CP_WAIT0();
        __syncthreads();

        int nxt = tile + gridDim.x;
        if (nxt < ntiles) {
            int bm = nxt * 128;
            uint32_t dstb = sbA + (uint32_t)((buf ^ 1) * ABUF) * 2;
            #pragma unroll
            for (int it = 0; it < 4; it++) {
                int lin = t + it * 512;
                int row = lin >> 4, c8 = (lin & 15) << 3;
                int gr = bm + row;
                int ok = (gr < N_NODES) ? 16 : 0;
                int gc = (gr < N_NODES) ? gr : (N_NODES - 1);
                cp_async16(dstb + (uint32_t)(row * AST + c8) * 2,
                           A + (size_t)gc * DF + c8, ok);
            }
        }
        CP_COMMIT();

        uint32_t abase = (uint32_t)(buf * ABUF) * 2;
        float acc[2][NJ][4];
        #pragma unroll
        for (int i = 0; i < 2; i++)
            #pragma unroll
            for (int j = 0; j < NJ; j++)
                #pragma unroll
                for (int q = 0; q < 4; q++) acc[i][j][q] = 0.f;

        #pragma unroll
        for (int k0 = 0; k0 < DF; k0 += 16) {
            uint32_t a[2][4], b[NJ][2];
            #pragma unroll
            for (int i = 0; i < 2; i++)
                ldsm_x4(a[i][0], a[i][1], a[i][2], a[i][3], aOff[i] + abase + k0 * 2);
            #pragma unroll
            for (int jj = 0; jj < NJ / 2; jj++)
                ldsm_x4(b[2 * jj][0], b[2 * jj][1], b[2 * jj + 1][0], b[2 * jj + 1][1],
                        bAddr[jj] + k0 * 2);
            if constexpr (NJ & 1)
                ldsm_x2(b[NJ - 1][0], b[NJ - 1][1], bAddr[NJ / 2] + k0 * 2);
            #pragma unroll
            for (int i = 0; i < 2; i++)
                #pragma unroll
                for (int j = 0; j < NJ; j++)
                    mma_bf16(acc[i][j], a[i], b[j]);
        }

        // ---- epilogue: stage fragments to smem (conflict-free), then
        //      fully-coalesced uint4 stores to P / R ----
        #pragma unroll
        for (int i = 0; i < 2; i++) {
            int r0 = wm + i * 16 + group;
            #pragma unroll
            for (int j = 0; j < NJ; j++) {
                int gn = wn + j * 8 + 2 * tig;
                *(uint32_t*)(St + r0 * BST2 + gn)       = pack_bf2(acc[i][j][0], acc[i][j][1]);
                *(uint32_t*)(St + (r0 + 8) * BST2 + gn) = pack_bf2(acc[i][j][2], acc[i][j][3]);
            }
        }
        __syncthreads();

        int bm = tile * 128;
        #pragma unroll
        for (int ch = t; ch < 128 * CPR; ch += 512) {
            int row = ch / CPR;
            int cc  = (ch % CPR) * 8;
            int gr  = bm + row;
            if (gr < N_NODES) {
                uint4 v = *(const uint4*)(St + row * BST2 + cc);
                if (cc < NPER) *(uint4*)(P + (size_t)gr * NPER + cc) = v;
                else           *(uint4*)(R + (size_t)gr * NPER + (cc - NPER)) = v;
            }
        }
        buf ^= 1;
        // loop-top __syncthreads (after CP_WAIT0) orders these staging reads
        // before the next tile's staging writes
    }
}

// -------- aggregation (hidden): OUT = relu(mean_nbr(P)+b+R) -----------------
__global__ void k_aggr(const __nv_bfloat16* __restrict__ P,
                       const __nv_bfloat16* __restrict__ R,
                       const float* __restrict__ bias,
                       __nv_bfloat16* __restrict__ OUT)
{
    int gw   = (blockIdx.x * blockDim.x + threadIdx.x) >> 5;
    int lane = threadIdx.x & 31;
    if (gw >= N_NODES) return;
    int start = g_rowptr[gw], end = g_rowptr[gw + 1];

    int c0 = lane << 2;
    const __nv_bfloat16* base = P + c0;
    float4 a0 = make_float4(0.f, 0.f, 0.f, 0.f);
    float4 a1 = make_float4(0.f, 0.f, 0.f, 0.f);
    int e = start;
    for (; e + 4 <= end; e += 4) {
        int i0 = g_col[e], i1 = g_col[e + 1], i2 = g_col[e + 2], i3 = g_col[e + 3];
        float4 p0 = ld_bf4(base + (size_t)i0 * DF);
        float4 p1 = ld_bf4(base + (size_t)i1 * DF);
        float4 p2 = ld_bf4(base + (size_t)i2 * DF);
        float4 p3 = ld_bf4(base + (size_t)i3 * DF);
        a0.x += p0.x; a0.y += p0.y; a0.z += p0.z; a0.w += p0.w;
        a1.x += p1.x; a1.y += p1.y; a1.z += p1.z; a1.w += p1.w;
        a0.x += p2.x; a0.y += p2.y; a0.z += p2.z; a0.w += p2.w;
        a1.x += p3.x; a1.y += p3.y; a1.z += p3.z; a1.w += p3.w;
    }
    for (; e < end; e++) {
        float4 p = ld_bf4(base + (size_t)g_col[e] * DF);
        a0.x += p.x; a0.y += p.y; a0.z += p.z; a0.w += p.w;
    }
    float inv = g_deginv[gw];
    float4 r = ld_bf4(R + (size_t)gw * DF + c0);
    float4 b = *(const float4*)(bias + c0);
    float4 ov;
    ov.x = fmaxf((a0.x + a1.x) * inv + b.x + r.x, 0.f);
    ov.y = fmaxf((a0.y + a1.y) * inv + b.y + r.y, 0.f);
    ov.z = fmaxf((a0.z + a1.z) * inv + b.z + r.z, 0.f);
    ov.w = fmaxf((a0.w + a1.w) * inv + b.w + r.w, 0.f);
    st_bf4(OUT + (size_t)gw * DF + c0, ov);
}

// -------- fused layer-2: aggr + L2-normalize + log_softmax ------------------
__global__ void k_aggr_out(const __nv_bfloat16* __restrict__ P,
                           const __nv_bfloat16* __restrict__ R,
                           const float* __restrict__ bias,
                           float* __restrict__ out)
{
    int gw   = (blockIdx.x * blockDim.x + threadIdx.x) >> 5;
    int lane = threadIdx.x & 31;
    if (gw >= N_NODES) return;
    bool act = (lane < 12);
    int c0 = lane << 2;

    float v[4] = {0.f, 0.f, 0.f, 0.f};
    if (act) {
        int start = g_rowptr[gw], end = g_rowptr[gw + 1];
        const __nv_bfloat16* base = P + c0;
        float4 a0 = make_float4(0.f, 0.f, 0.f, 0.f);
        float4 a1 = make_float4(0.f, 0.f, 0.f, 0.f);
        int e = start;
        for (; e + 4 <= end; e += 4) {
            int i0 = g_col[e], i1 = g_col[e + 1], i2 = g_col[e + 2], i3 = g_col[e + 3];
            float4 p0 = ld_bf4(base + (size_t)i0 * LDC2);
            float4 p1 = ld_bf4(base + (size_t)i1 * LDC2);
            float4 p2 = ld_bf4(base + (size_t)i2 * LDC2);
            float4 p3 = ld_bf4(base + (size_t)i3 * LDC2);
            a0.x += p0.x; a0.y += p0.y; a0.z += p0.z; a0.w += p0.w;
            a1.x += p1.x; a1.y += p1.y; a1.z += p1.z; a1.w += p1.w;
            a0.x += p2.x; a0.y += p2.y; a0.z += p2.z; a0.w += p2.w;
            a1.x += p3.x; a1.y += p3.y; a1.z += p3.z; a1.w += p3.w;
        }
        for (; e < end; e++) {
            float4 p = ld_bf4(base + (size_t)g_col[e] * LDC2);
            a0.x += p.x; a0.y += p.y; a0.z += p.z; a0.w += p.w;
        }
        float inv = g_deginv[gw];
        float4 r = ld_bf4(R + (size_t)gw * LDC2 + c0);
        float av[4] = {a0.x + a1.x, a0.y + a1.y, a0.z + a1.z, a0.w + a1.w};
        float rv[4] = {r.x, r.y, r.z, r.w};
        #pragma unroll
        for (int j = 0; j < 4; j++) {
            int cc = c0 + j;
            if (cc < NC) v[j] = av[j] * inv + bias[cc] + rv[j];
        }
    }

    float ss = v[0]*v[0] + v[1]*v[1] + v[2]*v[2] + v[3]*v[3];
    #pragma unroll
    for (int o = 16; o; o >>= 1) ss += __shfl_xor_sync(0xffffffffu, ss, o);
    float inv = 1.0f / fmaxf(sqrtf(ss), 1e-12f);
    #pragma unroll
    for (int j = 0; j < 4; j++) v[j] *= inv;

    float m = -1e30f;
    #pragma unroll
    for (int j = 0; j < 4; j++)
        if (act && (c0 + j) < NC) m = fmaxf(m, v[j]);
    #pragma unroll
    for (int o = 16; o; o >>= 1) m = fmaxf(m, __shfl_xor_sync(0xffffffffu, m, o));

    float s = 0.f;
    #pragma unroll
    for (int j = 0; j < 4; j++)
        if (act && (c0 + j) < NC) s += expf(v[j] - m);
    #pragma unroll
    for (int o = 16; o; o >>= 1) s += __shfl_xor_sync(0xffffffffu, s, o);
    float ls = m + logf(s);

    if (act) {
        #pragma unroll
        for (int j = 0; j < 4; j++) {
            int cc = c0 + j;
            if (cc < NC) out[(size_t)gw * NC + cc] = v[j] - ls;
        }
    }
}

// ---------------- host --------------------------------------------------------
extern "C" void kernel_launch(void* const* d_in, const int* in_sizes, int n_in,
                              void* d_out, int out_size)
{
    const float* x   = (const float*)d_in[0];
    const int*   ei  = (const int*)  d_in[1];
    const float* Wl0 = (const float*)d_in[2];
    const float* bl0 = (const float*)d_in[3];
    const float* Wr0 = (const float*)d_in[4];
    const float* Wl1 = (const float*)d_in[5];
    const float* bl1 = (const float*)d_in[6];
    const float* Wr1 = (const float*)d_in[7];
    const float* Wl2 = (const float*)d_in[8];
    const float* bl2 = (const float*)d_in[9];
    const float* Wr2 = (const float*)d_in[10];
    float* out = (float*)d_out;

    __nv_bfloat16 *P, *R, *H1, *H2, *Bt;
    cudaGetSymbolAddress((void**)&P,  g_P);
    cudaGetSymbolAddress((void**)&R,  g_R);
    cudaGetSymbolAddress((void**)&H1, g_H1);
    cudaGetSymbolAddress((void**)&H2, g_H2);
    cudaGetSymbolAddress((void**)&Bt, g_Bt);

    const int SMEM_G0   = (128 * 136 + 256 * 136) * 2;                       // 104448
    const int SMEM_P128 = (256 * 136 + 2 * 128 * 136 + 128 * 264) * 2;       // 206848
    const int SMEM_P48  = ( 96 * 136 + 2 * 128 * 136 + 128 * 104) * 2;       // 122368
    cudaFuncSetAttribute(k_gemm0,       cudaFuncAttributeMaxDynamicSharedMemorySize, SMEM_G0);
    cudaFuncSetAttribute(k_gemm_p<128>, cudaFuncAttributeMaxDynamicSharedMemorySize, SMEM_P128);
    cudaFuncSetAttribute(k_gemm_p<48>,  cudaFuncAttributeMaxDynamicSharedMemorySize, SMEM_P48);

    static cudaStream_t s1 = 0;
    static cudaEvent_t evFork = 0, evCSR = 0;
    if (!s1) {
        cudaStreamCreateWithFlags(&s1, cudaStreamNonBlocking);
        cudaEventCreateWithFlags(&evFork, cudaEventDisableTiming);
        cudaEventCreateWithFlags(&evCSR,  cudaEventDisableTiming);
    }

    int gmb = (N_NODES + 127) / 128;       // 391 tiles
    int agb = (N_NODES * 32 + 255) / 256;
    int epb = (N_EDGES / 2 + 255) / 256;   // 2 edges/thread

    // empty fork edge (required for capture): no kernel ahead of it
    cudaEventRecord(evFork, 0);
    cudaStreamWaitEvent(s1, evFork, 0);

    // side stream: CSR build starts immediately
    k_hist<<<epb, 256, 0, s1>>>(ei);
    k_scan_lb<<<(N_NODES + 1023) / 1024, 1024, 0, s1>>>();
    k_fill<<<epb, 256, 0, s1>>>(ei);
    cudaEventRecord(evCSR, s1);

    // main stream (parallel to CSR): weight images ONCE, then layer-0 GEMM
    k_prepB<<<(77824 + 255) / 256, 256>>>(Wl0, Wr0, Wl1, Wr1, Wl2, Wr2);
    k_gemm0<<<gmb, 512, SMEM_G0>>>(x, Bt, P, R);

    cudaStreamWaitEvent(0, evCSR, 0);
    k_aggr<<<agb, 256>>>(P, R, bl0, H1);
    // layer 1: persistent double-buffered GEMM, staged epilogue
    k_gemm_p<128><<<152, 512, SMEM_P128>>>(H1, Bt + 34816, P, R, gmb);
    k_aggr<<<agb, 256>>>(P, R, bl1, H2);
    // layer 2 (47 padded to 48; B image zero-pads col 47)
    k_gemm_p<48><<<152, 512, SMEM_P48>>>(H2, Bt + 69632, P, R, gmb);
    k_aggr_out<<<agb, 256>>>(P, R, bl2, out);
}